// round 4
// baseline (speedup 1.0000x reference)
#include <cuda_runtime.h>

#define HID   256
#define TLEN  128
#define TPAD  144            // padded row: cols 128..143 are permanent zeros
#define INCH  1024
#define CTXD  16

typedef unsigned long long ull;

#define HSM_FLOATS   (256 * TPAD)      // 36864
#define WSU_FLOATS   (256 * 68)        // 17408 (weight stage / scratch union)
#define SMEM_FLOATS  (HSM_FLOATS + WSU_FLOATS + TLEN + 64)

__device__ __forceinline__ ull fma2(ull a, ull b, ull c) {
    ull d;
    asm("fma.rn.f32x2 %0, %1, %2, %3;" : "=l"(d) : "l"(a), "l"(b), "l"(c));
    return d;
}
__device__ __forceinline__ ull pk(float lo, float hi) {
    ull d;
    asm("mov.b64 %0, {%1, %2};" : "=l"(d) : "f"(lo), "f"(hi));
    return d;
}
__device__ __forceinline__ void upk(float& lo, float& hi, ull v) {
    asm("mov.b64 {%0, %1}, %2;" : "=f"(lo), "=f"(hi) : "l"(v));
}
__device__ __forceinline__ void load8(float r[8], const float* p) {
    float4 a = *(const float4*)(p);
    float4 b = *(const float4*)(p + 4);
    r[0]=a.x; r[1]=a.y; r[2]=a.z; r[3]=a.w;
    r[4]=b.x; r[5]=b.y; r[6]=b.z; r[7]=b.w;
}
__device__ __forceinline__ void store8(float* p, const float r[8]) {
    *(float4*)(p)     = make_float4(r[0], r[1], r[2], r[3]);
    *(float4*)(p + 4) = make_float4(r[4], r[5], r[6], r[7]);
}

// One dilated conv layer on f32x2 packed math.
// Thread (mg,ng) owns out rows [o0,o0+8) x cols [t0,t0+8) (4 packed pairs).
template<int D>
__device__ __forceinline__ void conv_layer(
    float* __restrict__ hsm, float* __restrict__ wsu, float* __restrict__ colfac,
    const float* __restrict__ cw, const float* __restrict__ cb,
    int tid, int mg, int ng, int t0, int o0)
{
    ull acc[8][4];
    #pragma unroll
    for (int m = 0; m < 8; m++)
        #pragma unroll
        for (int jj = 0; jj < 4; jj++) acc[m][jj] = 0ull;

    const int o = tid >> 1, half = tid & 1;

    for (int kc = 0; kc < 16; kc++) {
        __syncthreads();   // previous chunk's weight reads / scratch use done
        // stage duplicated weights: wsu[o][68] rows hold {wx,wx,wy,wy} per input chan
        {
            const float4* src = (const float4*)(cw + o * (HID * 2) + kc * 32 + half * 16);
            float4 s0 = src[0], s1 = src[1], s2 = src[2], s3 = src[3];
            float f[16] = { s0.x,s0.y,s0.z,s0.w, s1.x,s1.y,s1.z,s1.w,
                            s2.x,s2.y,s2.z,s2.w, s3.x,s3.y,s3.z,s3.w };
            float* dst = wsu + o * 68 + half * 32;
            #pragma unroll
            for (int ii = 0; ii < 8; ii++)
                *(float4*)(dst + ii * 4) = make_float4(f[2*ii], f[2*ii], f[2*ii+1], f[2*ii+1]);
        }
        __syncthreads();

        #pragma unroll 2
        for (int i = 0; i < 16; i++) {
            const float* hrow = hsm + (kc * 16 + i) * TPAD;
            ull h1p[4], h2p[4];
            if constexpr (D == 1) {
                float4 a = *(const float4*)(hrow + t0);
                float4 b = *(const float4*)(hrow + t0 + 4);
                float r8 = hrow[t0 + 8];           // col 128 is zero-pad for ng=15
                h1p[0] = pk(a.x, a.y); h1p[1] = pk(a.z, a.w);
                h1p[2] = pk(b.x, b.y); h1p[3] = pk(b.z, b.w);
                h2p[0] = pk(a.y, a.z); h2p[1] = pk(a.w, b.x);
                h2p[2] = pk(b.y, b.z); h2p[3] = pk(b.w, r8);
            } else {
                ulonglong2 a = *(const ulonglong2*)(hrow + t0);
                ulonglong2 b = *(const ulonglong2*)(hrow + t0 + 4);
                h1p[0] = a.x; h1p[1] = a.y; h1p[2] = b.x; h1p[3] = b.y;
                if constexpr (D <= 16) {
                    if constexpr (D == 2) {
                        h2p[0] = *(const ull*)(hrow + t0 + 2);
                        h2p[1] = *(const ull*)(hrow + t0 + 4);
                        h2p[2] = *(const ull*)(hrow + t0 + 6);
                        h2p[3] = *(const ull*)(hrow + t0 + 8);
                    } else {   // D = 4, 8, 16: 16B-aligned, pad covers the tail
                        ulonglong2 c  = *(const ulonglong2*)(hrow + t0 + D);
                        ulonglong2 d2 = *(const ulonglong2*)(hrow + t0 + D + 4);
                        h2p[0] = c.x; h2p[1] = c.y; h2p[2] = d2.x; h2p[3] = d2.y;
                    }
                } else {       // D = 32, 64: group fully in-row (values may be pad zeros) or fully zero
                    if (t0 + D + 7 < TPAD) {
                        ulonglong2 c  = *(const ulonglong2*)(hrow + t0 + D);
                        ulonglong2 d2 = *(const ulonglong2*)(hrow + t0 + D + 4);
                        h2p[0] = c.x; h2p[1] = c.y; h2p[2] = d2.x; h2p[3] = d2.y;
                    } else {
                        h2p[0] = 0ull; h2p[1] = 0ull; h2p[2] = 0ull; h2p[3] = 0ull;
                    }
                }
            }
            const float* wr = wsu + o0 * 68 + i * 4;
            #pragma unroll
            for (int m = 0; m < 8; m++) {
                ull wx = *(const ull*)(wr + m * 68);
                ull wy = *(const ull*)(wr + m * 68 + 2);
                #pragma unroll
                for (int jj = 0; jj < 4; jj++) acc[m][jj] = fma2(wx, h1p[jj], acc[m][jj]);
                #pragma unroll
                for (int jj = 0; jj < 4; jj++) acc[m][jj] = fma2(wy, h2p[jj], acc[m][jj]);
            }
        }
    }
    __syncthreads();   // all weight reads done before wsu reused as scratch

    // epilogue: bias + leaky relu + skip + column sums of squares + unit-norm
    float accf[8][8];
    #pragma unroll
    for (int m = 0; m < 8; m++)
        #pragma unroll
        for (int jj = 0; jj < 4; jj++) upk(accf[m][2*jj], accf[m][2*jj+1], acc[m][jj]);

    float psum[8];
    #pragma unroll
    for (int j = 0; j < 8; j++) psum[j] = 0.f;
    #pragma unroll
    for (int m = 0; m < 8; m++) {
        float bb = cb[o0 + m];
        float sk[8];
        load8(sk, hsm + (o0 + m) * TPAD + t0);
        #pragma unroll
        for (int j = 0; j < 8; j++) {
            float y = accf[m][j] + bb;
            y = (y > 0.f) ? y : 0.2f * y;
            y += sk[j];
            accf[m][j] = y;
            psum[j] = fmaf(y, y, psum[j]);
        }
    }
    store8(wsu + mg * TLEN + t0, psum);     // scratch[32][128]
    __syncthreads();
    if (tid < TLEN) {
        float s = 0.f;
        #pragma unroll
        for (int g = 0; g < 32; g++) s += wsu[g * TLEN + tid];
        colfac[tid] = 1.0f / (sqrtf(s) + 1e-8f);
    }
    __syncthreads();
    float fac[8];
    load8(fac, colfac + t0);
    #pragma unroll
    for (int m = 0; m < 8; m++) {
        #pragma unroll
        for (int j = 0; j < 8; j++) accf[m][j] *= fac[j];
        store8(hsm + (o0 + m) * TPAD + t0, accf[m]);
    }
    __syncthreads();
}

__global__ __launch_bounds__(512, 1)
void Model_26147760898465_kernel(
    const float* __restrict__ x,
    const float* __restrict__ proj_w, const float* __restrict__ proj_b,
    const float* __restrict__ conv_w, const float* __restrict__ conv_b,
    const float* __restrict__ ev_w,  const float* __restrict__ ev_b,
    const float* __restrict__ sw_w,  const float* __restrict__ sw_b,
    float* __restrict__ out)
{
    extern __shared__ float sm[];
    float* hsm    = sm;
    float* wsu    = sm + HSM_FLOATS;
    float* colfac = wsu + WSU_FLOATS;
    float* redv   = colfac + TLEN;
    int*   redi   = (int*)(redv + 32);

    const int tid = threadIdx.x;
    const int b   = blockIdx.x;
    const int mg  = tid >> 4, ng = tid & 15;
    const int t0  = ng * 8,   o0 = mg * 8;

    // ---------------- 1x1 projection (f32x2): h = proj_w @ x[b] + proj_b ----------------
    {
        ull acc[8][4];
        #pragma unroll
        for (int m = 0; m < 8; m++)
            #pragma unroll
            for (int jj = 0; jj < 4; jj++) acc[m][jj] = 0ull;

        const float* xb  = x + (size_t)b * INCH * TLEN;
        float* xs  = wsu;            // [16][128]
        float* pws = wsu + 2048;     // [256][36] duplicated weight pairs
        const int o = tid >> 1, half = tid & 1;

        for (int kc = 0; kc < 64; kc++) {
            __syncthreads();
            ((float4*)xs)[tid] = ((const float4*)(xb + kc * 16 * TLEN))[tid];
            {
                const float4* src = (const float4*)(proj_w + o * INCH + kc * 16 + half * 8);
                float4 s0 = src[0], s1 = src[1];
                float f[8] = { s0.x,s0.y,s0.z,s0.w, s1.x,s1.y,s1.z,s1.w };
                float* dst = pws + o * 36 + half * 16;
                #pragma unroll
                for (int ii = 0; ii < 8; ii++)
                    *(float2*)(dst + ii * 2) = make_float2(f[ii], f[ii]);
            }
            __syncthreads();

            #pragma unroll 2
            for (int i = 0; i < 16; i++) {
                const float* xr = xs + i * TLEN;
                ulonglong2 a  = *(const ulonglong2*)(xr + t0);
                ulonglong2 bq = *(const ulonglong2*)(xr + t0 + 4);
                ull hp[4] = { a.x, a.y, bq.x, bq.y };
                const float* wr = pws + o0 * 36 + i * 2;
                #pragma unroll
                for (int m = 0; m < 8; m++) {
                    ull w = *(const ull*)(wr + m * 36);
                    #pragma unroll
                    for (int jj = 0; jj < 4; jj++) acc[m][jj] = fma2(w, hp[jj], acc[m][jj]);
                }
            }
        }
        __syncthreads();
        #pragma unroll
        for (int m = 0; m < 8; m++) {
            float r[8];
            #pragma unroll
            for (int jj = 0; jj < 4; jj++) upk(r[2*jj], r[2*jj+1], acc[m][jj]);
            float bb = proj_b[o0 + m];
            #pragma unroll
            for (int j = 0; j < 8; j++) r[j] += bb;
            store8(hsm + (o0 + m) * TPAD + t0, r);
        }
        // zero the pad columns (128..143) of every row — stays zero all layers
        {
            float z[8] = {0,0,0,0,0,0,0,0};
            int zr = tid >> 1;
            int zc = TLEN + (tid & 1) * 8;
            store8(hsm + zr * TPAD + zc, z);
        }
        __syncthreads();
    }

    // ---------------- dilated conv stack (DILATIONS = 1,2,4,8,16,32,64,1) ----------------
    conv_layer<1 >(hsm, wsu, colfac, conv_w + 0 * HID * HID * 2, conv_b + 0 * HID, tid, mg, ng, t0, o0);
    conv_layer<2 >(hsm, wsu, colfac, conv_w + 1 * HID * HID * 2, conv_b + 1 * HID, tid, mg, ng, t0, o0);
    conv_layer<4 >(hsm, wsu, colfac, conv_w + 2 * HID * HID * 2, conv_b + 2 * HID, tid, mg, ng, t0, o0);
    conv_layer<8 >(hsm, wsu, colfac, conv_w + 3 * HID * HID * 2, conv_b + 3 * HID, tid, mg, ng, t0, o0);
    conv_layer<16>(hsm, wsu, colfac, conv_w + 4 * HID * HID * 2, conv_b + 4 * HID, tid, mg, ng, t0, o0);
    conv_layer<32>(hsm, wsu, colfac, conv_w + 5 * HID * HID * 2, conv_b + 5 * HID, tid, mg, ng, t0, o0);
    conv_layer<64>(hsm, wsu, colfac, conv_w + 6 * HID * HID * 2, conv_b + 6 * HID, tid, mg, ng, t0, o0);
    conv_layer<1 >(hsm, wsu, colfac, conv_w + 7 * HID * HID * 2, conv_b + 7 * HID, tid, mg, ng, t0, o0);

    // ---------------- heads: event vectors, switch, top-1, outputs ----------------
    {
        // stage ev_w [16*256] and sw_w [256] into smem
        {
            float4* dst = (float4*)wsu;
            const float4* esrc = (const float4*)ev_w;
            dst[tid]       = esrc[tid];
            dst[tid + 512] = esrc[tid + 512];
            if (tid < 64) ((float4*)(wsu + 4096))[tid] = ((const float4*)sw_w)[tid];
        }
        __syncthreads();
        float* evs = wsu + 4096 + 256;   // [16][128]

        if (tid < TLEN) {
            float a[CTXD + 1];
            #pragma unroll
            for (int c = 0; c < CTXD; c++) a[c] = ev_b[c];
            a[CTXD] = sw_b[0];
            for (int i = 0; i < HID; i++) {
                float hv = hsm[i * TPAD + tid];
                #pragma unroll
                for (int c = 0; c < CTXD; c++) a[c] = fmaf(wsu[c * HID + i], hv, a[c]);
                a[CTXD] = fmaf(wsu[4096 + i], hv, a[CTXD]);
            }
            #pragma unroll
            for (int c = 0; c < CTXD; c++) evs[c * TLEN + tid] = a[c];
            colfac[tid] = fmaxf(a[CTXD], 0.f);   // attn = relu(switch)
        }
        __syncthreads();

        // top-1 over t with lowest-index tie-break (matches jax top_k)
        if (tid < TLEN) {
            float v = colfac[tid]; int idx = tid;
            #pragma unroll
            for (int off = 16; off > 0; off >>= 1) {
                float ov = __shfl_down_sync(0xffffffff, v, off);
                int   oi = __shfl_down_sync(0xffffffff, idx, off);
                if (ov > v || (ov == v && oi < idx)) { v = ov; idx = oi; }
            }
            if ((tid & 31) == 0) { redv[tid >> 5] = v; redi[tid >> 5] = idx; }
        }
        __syncthreads();
        if (tid == 0) {
            float v = redv[0]; int idx = redi[0];
            #pragma unroll
            for (int w = 1; w < 4; w++)
                if (redv[w] > v || (redv[w] == v && redi[w] < idx)) { v = redv[w]; idx = redi[w]; }
            redv[0] = v; redi[0] = idx;
        }
        __syncthreads();

        const int   bi = redi[0];
        const float bv = redv[0];
        // output: [vecs (B*CTX) | scheduling (B*T)]
        if (tid < CTXD) out[(size_t)b * CTXD + tid] = evs[tid * TLEN + bi];
        if (tid < TLEN) out[(size_t)gridDim.x * CTXD + (size_t)b * TLEN + tid] = (tid == bi) ? bv : 0.f;
    }
}

extern "C" void kernel_launch(void* const* d_in, const int* in_sizes, int n_in,
                              void* d_out, int out_size)
{
    const float* x      = (const float*)d_in[0];
    const float* proj_w = (const float*)d_in[1];
    const float* proj_b = (const float*)d_in[2];
    const float* conv_w = (const float*)d_in[3];
    const float* conv_b = (const float*)d_in[4];
    const float* ev_w   = (const float*)d_in[5];
    const float* ev_b   = (const float*)d_in[6];
    const float* sw_w   = (const float*)d_in[7];
    const float* sw_b   = (const float*)d_in[8];
    float* out = (float*)d_out;

    const int B = in_sizes[0] / (INCH * TLEN);   // 256
    const size_t smem = SMEM_FLOATS * sizeof(float);   // ~218 KB
    cudaFuncSetAttribute(Model_26147760898465_kernel,
                         cudaFuncAttributeMaxDynamicSharedMemorySize, (int)smem);
    Model_26147760898465_kernel<<<B, 512, smem>>>(
        x, proj_w, proj_b, conv_w, conv_b, ev_w, ev_b, sw_w, sw_b, out);
}

// round 6
// speedup vs baseline: 3.2265x; 3.2265x over previous
#include <cuda_runtime.h>
#include <cuda_bf16.h>
#include <cstdint>

#define TLEN 128
#define HID  256
#define CTXD 16

#define SBW   280            // B row stride, bf16 units (560 bytes)
#define SBB   560            // B row stride, bytes
#define SAB   144            // A row stride, bytes (72 bf16)
#define BSPL  73920          // one B split: 132 rows * 560B
#define ASMO  147840         // A buffer offset in smem
#define ALO   36864          // lo-split offset within A buffer
#define CHUNK_B 73728        // staged A chunk (hi+lo)
#define SMEM_BYTES 221568

__device__ __align__(1024) unsigned char gW[80ull * CHUNK_B];   // 5.9 MB pre-split weights

__device__ __forceinline__ void mma_bf16(float* d, uint32_t a0, uint32_t a1, uint32_t a2, uint32_t a3,
                                         uint32_t b0, uint32_t b1) {
    asm("mma.sync.aligned.m16n8k16.row.col.f32.bf16.bf16.f32 "
        "{%0,%1,%2,%3}, {%4,%5,%6,%7}, {%8,%9}, {%0,%1,%2,%3};"
        : "+f"(d[0]), "+f"(d[1]), "+f"(d[2]), "+f"(d[3])
        : "r"(a0), "r"(a1), "r"(a2), "r"(a3), "r"(b0), "r"(b1));
}
__device__ __forceinline__ void split2(float w, __nv_bfloat16& hi, __nv_bfloat16& lo) {
    hi = __float2bfloat16(w);
    lo = __float2bfloat16(w - __bfloat162float(hi));
}

// ---------------- prep: split weights into A-chunk images ----------------
// chunk g<64: conv layer l=g/8, c=g%8 (tap=c/4, chanblk=c%4). g>=64: proj chunk c=g-64.
__global__ void prep_kernel(const float* __restrict__ conv_w, const float* __restrict__ proj_w) {
    const int g = blockIdx.x, tid = threadIdx.x;
    unsigned char* dst = gW + (size_t)g * CHUNK_B;
    for (int i = 0; i < 64; i++) {
        int e = i * 256 + tid;          // 0..16383
        int m = e >> 6, kk = e & 63;
        float w;
        if (g < 64) {
            int l = g >> 3, c = g & 7, tap = c >> 2, cb = c & 3;
            w = conv_w[(((size_t)(l * 256 + m)) * 256 + cb * 64 + kk) * 2 + tap];
        } else {
            w = proj_w[(size_t)m * 1024 + (g - 64) * 64 + kk];
        }
        __nv_bfloat16 hi, lo; split2(w, hi, lo);
        *(__nv_bfloat16*)(dst + m * SAB + kk * 2) = hi;
        *(__nv_bfloat16*)(dst + ALO + m * SAB + kk * 2) = lo;
    }
}

// ---------------- device helpers ----------------
__device__ __forceinline__ void stageA(unsigned char* sm, int g, int tid) {
    uint32_t dst = (uint32_t)__cvta_generic_to_shared(sm + ASMO) + tid * 16;
    const unsigned char* src = gW + (size_t)g * CHUNK_B + tid * 16;
    #pragma unroll
    for (int i = 0; i < 18; i++)
        asm volatile("cp.async.cg.shared.global [%0], [%1], 16;"
                     :: "r"(dst + i * 4096), "l"(src + i * 4096));
    asm volatile("cp.async.commit_group;");
    asm volatile("cp.async.wait_group 0;");
}

__device__ __forceinline__ void gemm_chunk(
    float (&d)[4][8][4], const unsigned char* sm,
    int mo, int to, int gr, int lc, int chanbase, int shift, int nvalid)
{
    const unsigned char* A  = sm + ASMO;
    const unsigned char* Bh = sm;
    const unsigned char* Bl = sm + BSPL;
    #pragma unroll
    for (int kblk = 0; kblk < 4; kblk++) {
        uint32_t ah[4][4], al[4][4];
        #pragma unroll
        for (int mi = 0; mi < 4; mi++) {
            int ab = (mo + mi * 16 + gr) * SAB + kblk * 32 + lc * 4;
            ah[mi][0] = *(const uint32_t*)(A + ab);
            ah[mi][1] = *(const uint32_t*)(A + ab + 8 * SAB);
            ah[mi][2] = *(const uint32_t*)(A + ab + 16);
            ah[mi][3] = *(const uint32_t*)(A + ab + 8 * SAB + 16);
            al[mi][0] = *(const uint32_t*)(A + ALO + ab);
            al[mi][1] = *(const uint32_t*)(A + ALO + ab + 8 * SAB);
            al[mi][2] = *(const uint32_t*)(A + ALO + ab + 16);
            al[mi][3] = *(const uint32_t*)(A + ALO + ab + 8 * SAB + 16);
        }
        const int cb2 = (chanbase + kblk * 16 + lc * 2) * 2;
        #pragma unroll
        for (int ni = 0; ni < 8; ni++) {
            if (ni < nvalid) {
                int bb = (to + ni * 8 + gr + shift) * SBB + cb2;
                uint32_t bh0 = *(const uint32_t*)(Bh + bb);
                uint32_t bh1 = *(const uint32_t*)(Bh + bb + 16);
                uint32_t bl0 = *(const uint32_t*)(Bl + bb);
                uint32_t bl1 = *(const uint32_t*)(Bl + bb + 16);
                #pragma unroll
                for (int mi = 0; mi < 4; mi++) {
                    mma_bf16(d[mi][ni], ah[mi][0], ah[mi][1], ah[mi][2], ah[mi][3], bh0, bh1);
                    mma_bf16(d[mi][ni], al[mi][0], al[mi][1], al[mi][2], al[mi][3], bh0, bh1);
                    mma_bf16(d[mi][ni], ah[mi][0], ah[mi][1], ah[mi][2], ah[mi][3], bl0, bl1);
                }
            }
        }
    }
}

// ---------------- main ----------------
__global__ __launch_bounds__(256, 1)
void Model_26147760898465_kernel(
    const float* __restrict__ x,
    const float* __restrict__ proj_b, const float* __restrict__ conv_b,
    const float* __restrict__ ev_w,  const float* __restrict__ ev_b,
    const float* __restrict__ sw_w,  const float* __restrict__ sw_b,
    float* __restrict__ out)
{
    extern __shared__ unsigned char sm[];
    __nv_bfloat16* Bhi = (__nv_bfloat16*)sm;
    __nv_bfloat16* Blo = (__nv_bfloat16*)(sm + BSPL);

    const int tid = threadIdx.x, warp = tid >> 5, lane = tid & 31;
    const int gr = lane >> 2, lc = lane & 3, b = blockIdx.x;
    const int mo = (warp & 3) * 64, to = (warp >> 2) * 64;

    // zero pad rows 128..131 of both B splits (stay zero forever)
    for (int i = tid; i < 4 * SBW; i += 256) {
        Bhi[128 * SBW + i] = __float2bfloat16(0.f);
        Blo[128 * SBW + i] = __float2bfloat16(0.f);
    }

    float d[4][8][4];

    // ======== projection: D = proj_w @ x[b], K=1024 in 4 passes ========
    #pragma unroll
    for (int mi = 0; mi < 4; mi++)
        #pragma unroll
        for (int ni = 0; ni < 8; ni++)
            #pragma unroll
            for (int r = 0; r < 4; r++) d[mi][ni][r] = 0.f;

    for (int pass = 0; pass < 4; pass++) {
        __syncthreads();   // previous pass's B reads done
        {   // build B from x: thread -> 2 chans, 64 t's
            int cp = tid & 127, th = tid >> 7;
            int c0 = cp * 2;
            const float* xp0 = x + ((size_t)b * 1024 + pass * 256 + c0) * TLEN;
            const float* xp1 = xp0 + TLEN;
            for (int q = 0; q < 16; q++) {
                int t = th * 64 + q * 4;
                float4 v0 = *(const float4*)(xp0 + t);
                float4 v1 = *(const float4*)(xp1 + t);
                float a0[4] = {v0.x, v0.y, v0.z, v0.w};
                float a1[4] = {v1.x, v1.y, v1.z, v1.w};
                #pragma unroll
                for (int j = 0; j < 4; j++) {
                    __nv_bfloat16 h0, l0, h1, l1;
                    split2(a0[j], h0, l0); split2(a1[j], h1, l1);
                    ((uint32_t*)Bhi)[(t + j) * (SBW / 2) + cp] =
                        (uint32_t)__bfloat16_as_ushort(h0) | ((uint32_t)__bfloat16_as_ushort(h1) << 16);
                    ((uint32_t*)Blo)[(t + j) * (SBW / 2) + cp] =
                        (uint32_t)__bfloat16_as_ushort(l0) | ((uint32_t)__bfloat16_as_ushort(l1) << 16);
                }
            }
        }
        __syncthreads();
        for (int sc = 0; sc < 4; sc++) {
            stageA(sm, 64 + pass * 4 + sc, tid);
            __syncthreads();
            gemm_chunk(d, sm, mo, to, gr, lc, sc * 64, 0, 8);
            __syncthreads();
        }
    }
    // proj epilogue: bias, write splits into B
    {
        float bias[4][2];
        #pragma unroll
        for (int mi = 0; mi < 4; mi++) {
            bias[mi][0] = __ldg(proj_b + mo + mi * 16 + gr);
            bias[mi][1] = __ldg(proj_b + mo + mi * 16 + gr + 8);
        }
        #pragma unroll
        for (int mi = 0; mi < 4; mi++)
            #pragma unroll
            for (int ni = 0; ni < 8; ni++)
                #pragma unroll
                for (int r = 0; r < 4; r++) {
                    int m = mo + mi * 16 + gr + (r >> 1) * 8;
                    int t = to + ni * 8 + lc * 2 + (r & 1);
                    float y = d[mi][ni][r] + bias[mi][r >> 1];
                    __nv_bfloat16 hi, lo; split2(y, hi, lo);
                    Bhi[t * SBW + m] = hi; Blo[t * SBW + m] = lo;
                }
        __syncthreads();
    }

    // ======== 8 dilated conv layers ========
    const int DILS[8] = {1, 2, 4, 8, 16, 32, 64, 1};
    for (int l = 0; l < 8; l++) {
        const int D = DILS[l];
        #pragma unroll
        for (int mi = 0; mi < 4; mi++)
            #pragma unroll
            for (int ni = 0; ni < 8; ni++)
                #pragma unroll
                for (int r = 0; r < 4; r++) d[mi][ni][r] = 0.f;

        for (int c = 0; c < 8; c++) {
            stageA(sm, l * 8 + c, tid);
            __syncthreads();
            int tap = c >> 2, cb = c & 3;
            int shift = tap ? D : 0;
            int nv = 8;
            if (tap && D >= 8) { int nn = (128 - D - to) >> 3; nv = nn < 0 ? 0 : (nn > 8 ? 8 : nn); }
            gemm_chunk(d, sm, mo, to, gr, lc, cb * 64, shift, nv);
            __syncthreads();
        }

        // epilogue: bias + leaky + skip + unit-norm, write new splits
        float* scr = (float*)(sm + ASMO);        // [4][128]
        float* colfac = scr + 512;
        float bias[4][2];
        #pragma unroll
        for (int mi = 0; mi < 4; mi++) {
            bias[mi][0] = __ldg(conv_b + l * HID + mo + mi * 16 + gr);
            bias[mi][1] = __ldg(conv_b + l * HID + mo + mi * 16 + gr + 8);
        }
        float ps[8][2];
        #pragma unroll
        for (int ni = 0; ni < 8; ni++) { ps[ni][0] = 0.f; ps[ni][1] = 0.f; }
        #pragma unroll
        for (int mi = 0; mi < 4; mi++)
            #pragma unroll
            for (int ni = 0; ni < 8; ni++)
                #pragma unroll
                for (int r = 0; r < 4; r++) {
                    int m = mo + mi * 16 + gr + (r >> 1) * 8;
                    int t = to + ni * 8 + lc * 2 + (r & 1);
                    float y = d[mi][ni][r] + bias[mi][r >> 1];
                    y = (y > 0.f) ? y : 0.2f * y;
                    y += __bfloat162float(Bhi[t * SBW + m]) + __bfloat162float(Blo[t * SBW + m]);
                    d[mi][ni][r] = y;
                    ps[ni][r & 1] = fmaf(y, y, ps[ni][r & 1]);
                }
        #pragma unroll
        for (int ni = 0; ni < 8; ni++)
            #pragma unroll
            for (int j = 0; j < 2; j++) {
                float v = ps[ni][j];
                v += __shfl_down_sync(0xffffffffu, v, 16);
                v += __shfl_down_sync(0xffffffffu, v, 8);
                v += __shfl_down_sync(0xffffffffu, v, 4);
                ps[ni][j] = v;
            }
        if (lane < 4) {
            #pragma unroll
            for (int ni = 0; ni < 8; ni++)
                #pragma unroll
                for (int j = 0; j < 2; j++)
                    scr[(warp & 3) * 128 + to + ni * 8 + lane * 2 + j] = ps[ni][j];
        }
        __syncthreads();
        if (tid < TLEN) {
            float s = scr[tid] + scr[128 + tid] + scr[256 + tid] + scr[384 + tid];
            colfac[tid] = 1.0f / (sqrtf(s) + 1e-8f);
        }
        __syncthreads();
        float cf[8][2];
        #pragma unroll
        for (int ni = 0; ni < 8; ni++) {
            cf[ni][0] = colfac[to + ni * 8 + lc * 2];
            cf[ni][1] = colfac[to + ni * 8 + lc * 2 + 1];
        }
        __syncthreads();   // all colfac reads done before B overwrite below racing? (writes go to B, not scr/colfac — safe; keep for ordering)
        #pragma unroll
        for (int mi = 0; mi < 4; mi++)
            #pragma unroll
            for (int ni = 0; ni < 8; ni++)
                #pragma unroll
                for (int r = 0; r < 4; r++) {
                    int m = mo + mi * 16 + gr + (r >> 1) * 8;
                    int t = to + ni * 8 + lc * 2 + (r & 1);
                    float y = d[mi][ni][r] * cf[ni][r & 1];
                    __nv_bfloat16 hi, lo; split2(y, hi, lo);
                    Bhi[t * SBW + m] = hi; Blo[t * SBW + m] = lo;
                }
        __syncthreads();
    }

    // ======== heads ========
    float* evw = (float*)(sm + ASMO);          // 16x256
    float* sww = evw + CTXD * HID;             // 256
    float* evs = sww + HID;                    // 16x128
    float* attn = evs + CTXD * TLEN;           // 128
    float* redv = attn + TLEN;                 // 4
    int*   redi = (int*)(redv + 8);
    {
        float4* dst = (float4*)evw;
        const float4* src = (const float4*)ev_w;
        #pragma unroll
        for (int i = 0; i < 4; i++) dst[tid + i * 256] = src[tid + i * 256];
        if (tid < 64) ((float4*)sww)[tid] = ((const float4*)sw_w)[tid];
    }
    __syncthreads();
    if (tid < TLEN) {
        float a[CTXD + 1];
        #pragma unroll
        for (int cc = 0; cc < CTXD; cc++) a[cc] = __ldg(ev_b + cc);
        a[CTXD] = __ldg(sw_b);
        for (int i = 0; i < HID; i++) {
            float hv = __bfloat162float(Bhi[tid * SBW + i]) + __bfloat162float(Blo[tid * SBW + i]);
            #pragma unroll
            for (int cc = 0; cc < CTXD; cc++) a[cc] = fmaf(evw[cc * HID + i], hv, a[cc]);
            a[CTXD] = fmaf(sww[i], hv, a[CTXD]);
        }
        #pragma unroll
        for (int cc = 0; cc < CTXD; cc++) evs[cc * TLEN + tid] = a[cc];
        attn[tid] = fmaxf(a[CTXD], 0.f);
    }
    __syncthreads();
    if (tid < TLEN) {
        float v = attn[tid]; int idx = tid;
        #pragma unroll
        for (int off = 16; off > 0; off >>= 1) {
            float ov = __shfl_down_sync(0xffffffffu, v, off);
            int   oi = __shfl_down_sync(0xffffffffu, idx, off);
            if (ov > v || (ov == v && oi < idx)) { v = ov; idx = oi; }
        }
        if (lane == 0) { redv[warp] = v; redi[warp] = idx; }
    }
    __syncthreads();
    if (tid == 0) {
        float v = redv[0]; int idx = redi[0];
        for (int w = 1; w < 4; w++)
            if (redv[w] > v || (redv[w] == v && redi[w] < idx)) { v = redv[w]; idx = redi[w]; }
        redv[0] = v; redi[0] = idx;
    }
    __syncthreads();
    const int bi = redi[0]; const float bv = redv[0];
    if (tid < CTXD) out[(size_t)b * CTXD + tid] = evs[tid * TLEN + bi];
    if (tid < TLEN) out[(size_t)gridDim.x * CTXD + (size_t)b * TLEN + tid] = (tid == bi) ? bv : 0.f;
}

extern "C" void kernel_launch(void* const* d_in, const int* in_sizes, int n_in,
                              void* d_out, int out_size)
{
    const float* x      = (const float*)d_in[0];
    const float* proj_w = (const float*)d_in[1];
    const float* proj_b = (const float*)d_in[2];
    const float* conv_w = (const float*)d_in[3];
    const float* conv_b = (const float*)d_in[4];
    const float* ev_w   = (const float*)d_in[5];
    const float* ev_b   = (const float*)d_in[6];
    const float* sw_w   = (const float*)d_in[7];
    const float* sw_b   = (const float*)d_in[8];
    float* out = (float*)d_out;
    const int B = in_sizes[0] / (1024 * TLEN);   // 256

    prep_kernel<<<80, 256>>>(conv_w, proj_w);
    cudaFuncSetAttribute(Model_26147760898465_kernel,
                         cudaFuncAttributeMaxDynamicSharedMemorySize, SMEM_BYTES);
    Model_26147760898465_kernel<<<B, 256, SMEM_BYTES>>>(
        x, proj_b, conv_b, ev_w, ev_b, sw_w, sw_b, out);
}

// round 7
// speedup vs baseline: 3.4915x; 1.0821x over previous
#include <cuda_runtime.h>
#include <cuda_bf16.h>
#include <cstdint>

#define TLEN 128
#define HID  256
#define CTXD 16

#define SBW   280              // B row stride, bf16 units
#define SBB   560              // B row stride, bytes
#define SAB   80               // A row stride, bytes (32 k-units + pad) — conflict-free
#define BSPL  73920            // one B split: 132 rows * 560B
#define ASPL  20480            // one A split: 256 rows * 80B
#define HCH_B 40960            // half-chunk (hi+lo splits)
#define A0_OFF 147840
#define A1_OFF (A0_OFF + HCH_B)        // 188800
#define SCR_OFF (A1_OFF + HCH_B)       // 229760 (dedicated epilogue scratch)
#define CF_OFF  (SCR_OFF + 2048)       // 231808
#define RV_OFF  (CF_OFF + 512)         // 232320
#define RI_OFF  (RV_OFF + 16)          // 232336
#define SMEM_BYTES (RI_OFF + 16)       // 232352  (< 232448 opt-in cap)

__device__ __align__(1024) unsigned char gW[160ull * HCH_B];   // 6.55 MB pre-split weights

__device__ __forceinline__ void mma_bf16(float* d, uint32_t a0, uint32_t a1, uint32_t a2, uint32_t a3,
                                         uint32_t b0, uint32_t b1) {
    asm("mma.sync.aligned.m16n8k16.row.col.f32.bf16.bf16.f32 "
        "{%0,%1,%2,%3}, {%4,%5,%6,%7}, {%8,%9}, {%0,%1,%2,%3};"
        : "+f"(d[0]), "+f"(d[1]), "+f"(d[2]), "+f"(d[3])
        : "r"(a0), "r"(a1), "r"(a2), "r"(a3), "r"(b0), "r"(b1));
}
__device__ __forceinline__ void split2(float w, __nv_bfloat16& hi, __nv_bfloat16& lo) {
    hi = __float2bfloat16(w);
    lo = __float2bfloat16(w - __bfloat162float(hi));
}

// ---------------- prep: split weights into half-chunk images ----------------
// g<128: conv — l=g>>4, c=g&15, tap=c>>3, kb=c&7 (32 chans). g>=128: proj — p=g-128, chans p*32..+32.
__global__ void prep_kernel(const float* __restrict__ conv_w, const float* __restrict__ proj_w) {
    const int g = blockIdx.x, tid = threadIdx.x;
    unsigned char* dst = gW + (size_t)g * HCH_B;
    for (int i = 0; i < 32; i++) {
        int e = i * 256 + tid;          // 0..8191
        int m = e >> 5, kk = e & 31;
        float w;
        if (g < 128) {
            int l = g >> 4, c = g & 15, tap = c >> 3, kb = c & 7;
            w = conv_w[(((size_t)(l * 256 + m)) * 256 + kb * 32 + kk) * 2 + tap];
        } else {
            int p = g - 128;
            w = proj_w[(size_t)m * 1024 + p * 32 + kk];
        }
        __nv_bfloat16 hi, lo; split2(w, hi, lo);
        *(__nv_bfloat16*)(dst + m * SAB + kk * 2) = hi;
        *(__nv_bfloat16*)(dst + ASPL + m * SAB + kk * 2) = lo;
    }
}

// ---------------- pipeline helpers ----------------
__device__ __forceinline__ int gseq(int s) { return (s < 32) ? 128 + s : s - 32; }

__device__ __forceinline__ void stage_issue(unsigned char* smbuf, int g, int tid) {
    uint32_t dst = (uint32_t)__cvta_generic_to_shared(smbuf) + tid * 16;
    const unsigned char* src = gW + (size_t)g * HCH_B + tid * 16;
    #pragma unroll
    for (int i = 0; i < 10; i++)
        asm volatile("cp.async.cg.shared.global [%0], [%1], 16;"
                     :: "r"(dst + i * 4096), "l"(src + i * 4096));
    asm volatile("cp.async.commit_group;");
}
__device__ __forceinline__ void wait1() { asm volatile("cp.async.wait_group 1;" ::: "memory"); }
__device__ __forceinline__ void wait0() { asm volatile("cp.async.wait_group 0;" ::: "memory"); }

__device__ __forceinline__ void gemm32(
    float (&d)[4][8][4], const unsigned char* sm, const unsigned char* A,
    int mo, int to, int gr, int lc, int chanbase, int shift, int nvalid)
{
    const unsigned char* Bh = sm;
    const unsigned char* Bl = sm + BSPL;
    #pragma unroll
    for (int kblk = 0; kblk < 2; kblk++) {
        uint32_t ah[4][4], al[4][4];
        #pragma unroll
        for (int mi = 0; mi < 4; mi++) {
            int ab = (mo + mi * 16 + gr) * SAB + kblk * 32 + lc * 4;
            ah[mi][0] = *(const uint32_t*)(A + ab);
            ah[mi][1] = *(const uint32_t*)(A + ab + 8 * SAB);
            ah[mi][2] = *(const uint32_t*)(A + ab + 16);
            ah[mi][3] = *(const uint32_t*)(A + ab + 8 * SAB + 16);
            al[mi][0] = *(const uint32_t*)(A + ASPL + ab);
            al[mi][1] = *(const uint32_t*)(A + ASPL + ab + 8 * SAB);
            al[mi][2] = *(const uint32_t*)(A + ASPL + ab + 16);
            al[mi][3] = *(const uint32_t*)(A + ASPL + ab + 8 * SAB + 16);
        }
        const int cb2 = (chanbase + kblk * 16 + lc * 2) * 2;
        #pragma unroll
        for (int ni = 0; ni < 8; ni++) {
            if (ni < nvalid) {
                int bb = (to + ni * 8 + gr + shift) * SBB + cb2;
                uint32_t bh0 = *(const uint32_t*)(Bh + bb);
                uint32_t bh1 = *(const uint32_t*)(Bh + bb + 16);
                uint32_t bl0 = *(const uint32_t*)(Bl + bb);
                uint32_t bl1 = *(const uint32_t*)(Bl + bb + 16);
                #pragma unroll
                for (int mi = 0; mi < 4; mi++) {
                    mma_bf16(d[mi][ni], ah[mi][0], ah[mi][1], ah[mi][2], ah[mi][3], bh0, bh1);
                    mma_bf16(d[mi][ni], al[mi][0], al[mi][1], al[mi][2], al[mi][3], bh0, bh1);
                    mma_bf16(d[mi][ni], ah[mi][0], ah[mi][1], ah[mi][2], ah[mi][3], bl0, bl1);
                }
            }
        }
    }
}

// ---------------- main ----------------
__global__ __launch_bounds__(256, 1)
void Model_26147760898465_kernel(
    const float* __restrict__ x,
    const float* __restrict__ proj_b, const float* __restrict__ conv_b,
    const float* __restrict__ ev_w,  const float* __restrict__ ev_b,
    const float* __restrict__ sw_w,  const float* __restrict__ sw_b,
    float* __restrict__ out)
{
    extern __shared__ unsigned char sm[];
    __nv_bfloat16* Bhi = (__nv_bfloat16*)sm;
    __nv_bfloat16* Blo = (__nv_bfloat16*)(sm + BSPL);

    const int tid = threadIdx.x, warp = tid >> 5, lane = tid & 31;
    const int gr = lane >> 2, lc = lane & 3, b = blockIdx.x;
    const int mo = (warp & 3) * 64, to = (warp >> 2) * 64;

    // kick off pipeline: chunks for steps 0,1 (proj)
    stage_issue(sm + A0_OFF, gseq(0), tid);
    stage_issue(sm + A1_OFF, gseq(1), tid);

    // zero pad rows 128..131 of both B splits (stay zero forever)
    for (int i = tid; i < 4 * SBW; i += 256) {
        Bhi[128 * SBW + i] = __float2bfloat16(0.f);
        Blo[128 * SBW + i] = __float2bfloat16(0.f);
    }

    float d[4][8][4];

    // ======== projection: K=1024 in 4 passes of 256 chans (8 half-chunks each) ========
    #pragma unroll
    for (int mi = 0; mi < 4; mi++)
        #pragma unroll
        for (int ni = 0; ni < 8; ni++)
            #pragma unroll
            for (int r = 0; r < 4; r++) d[mi][ni][r] = 0.f;

    for (int pass = 0; pass < 4; pass++) {
        __syncthreads();   // previous pass's B reads done
        {   // build B from x: thread -> 2 chans, 64 t's
            int cp = tid & 127, th = tid >> 7;
            int c0 = cp * 2;
            const float* xp0 = x + ((size_t)b * 1024 + pass * 256 + c0) * TLEN;
            const float* xp1 = xp0 + TLEN;
            for (int q = 0; q < 16; q++) {
                int t = th * 64 + q * 4;
                float4 v0 = *(const float4*)(xp0 + t);
                float4 v1 = *(const float4*)(xp1 + t);
                float a0[4] = {v0.x, v0.y, v0.z, v0.w};
                float a1[4] = {v1.x, v1.y, v1.z, v1.w};
                #pragma unroll
                for (int j = 0; j < 4; j++) {
                    __nv_bfloat16 h0, l0, h1, l1;
                    split2(a0[j], h0, l0); split2(a1[j], h1, l1);
                    ((uint32_t*)Bhi)[(t + j) * (SBW / 2) + cp] =
                        (uint32_t)__bfloat16_as_ushort(h0) | ((uint32_t)__bfloat16_as_ushort(h1) << 16);
                    ((uint32_t*)Blo)[(t + j) * (SBW / 2) + cp] =
                        (uint32_t)__bfloat16_as_ushort(l0) | ((uint32_t)__bfloat16_as_ushort(l1) << 16);
                }
            }
        }
        __syncthreads();
        for (int hc = 0; hc < 8; hc++) {
            int st = pass * 8 + hc;
            wait1();
            __syncthreads();
            gemm32(d, sm, sm + ((st & 1) ? A1_OFF : A0_OFF), mo, to, gr, lc, hc * 32, 0, 8);
            __syncthreads();
            stage_issue(sm + ((st & 1) ? A1_OFF : A0_OFF), gseq(st + 2), tid);
        }
    }
    // proj epilogue: bias, write splits into B
    {
        float bias[4][2];
        #pragma unroll
        for (int mi = 0; mi < 4; mi++) {
            bias[mi][0] = __ldg(proj_b + mo + mi * 16 + gr);
            bias[mi][1] = __ldg(proj_b + mo + mi * 16 + gr + 8);
        }
        #pragma unroll
        for (int mi = 0; mi < 4; mi++)
            #pragma unroll
            for (int ni = 0; ni < 8; ni++)
                #pragma unroll
                for (int r = 0; r < 4; r++) {
                    int m = mo + mi * 16 + gr + (r >> 1) * 8;
                    int t = to + ni * 8 + lc * 2 + (r & 1);
                    float y = d[mi][ni][r] + bias[mi][r >> 1];
                    __nv_bfloat16 hi, lo; split2(y, hi, lo);
                    Bhi[t * SBW + m] = hi; Blo[t * SBW + m] = lo;
                }
        __syncthreads();
    }

    // ======== 8 dilated conv layers (16 half-chunks each) ========
    const int DILS[8] = {1, 2, 4, 8, 16, 32, 64, 1};
    for (int l = 0; l < 8; l++) {
        const int D = DILS[l];
        #pragma unroll
        for (int mi = 0; mi < 4; mi++)
            #pragma unroll
            for (int ni = 0; ni < 8; ni++)
                #pragma unroll
                for (int r = 0; r < 4; r++) d[mi][ni][r] = 0.f;

        for (int c = 0; c < 16; c++) {
            int st = 32 + l * 16 + c;
            if (st == 159) wait0(); else wait1();
            __syncthreads();
            int tap = c >> 3, kb = c & 7;
            int shift = tap ? D : 0;
            int nv = 8;
            if (tap && D >= 8) { int nn = (128 - D - to) >> 3; nv = nn < 0 ? 0 : (nn > 8 ? 8 : nn); }
            gemm32(d, sm, sm + ((st & 1) ? A1_OFF : A0_OFF), mo, to, gr, lc, kb * 32, shift, nv);
            __syncthreads();
            if (st + 2 < 160)
                stage_issue(sm + ((st & 1) ? A1_OFF : A0_OFF), gseq(st + 2), tid);
        }

        // epilogue: bias + leaky + skip + unit-norm, write new splits (overlaps next-layer staging)
        float* scr = (float*)(sm + SCR_OFF);     // [4][128]
        float* colfac = (float*)(sm + CF_OFF);
        float bias[4][2];
        #pragma unroll
        for (int mi = 0; mi < 4; mi++) {
            bias[mi][0] = __ldg(conv_b + l * HID + mo + mi * 16 + gr);
            bias[mi][1] = __ldg(conv_b + l * HID + mo + mi * 16 + gr + 8);
        }
        float ps[8][2];
        #pragma unroll
        for (int ni = 0; ni < 8; ni++) { ps[ni][0] = 0.f; ps[ni][1] = 0.f; }
        #pragma unroll
        for (int mi = 0; mi < 4; mi++)
            #pragma unroll
            for (int ni = 0; ni < 8; ni++)
                #pragma unroll
                for (int r = 0; r < 4; r++) {
                    int m = mo + mi * 16 + gr + (r >> 1) * 8;
                    int t = to + ni * 8 + lc * 2 + (r & 1);
                    float y = d[mi][ni][r] + bias[mi][r >> 1];
                    y = (y > 0.f) ? y : 0.2f * y;
                    y += __bfloat162float(Bhi[t * SBW + m]) + __bfloat162float(Blo[t * SBW + m]);
                    d[mi][ni][r] = y;
                    ps[ni][r & 1] = fmaf(y, y, ps[ni][r & 1]);
                }
        #pragma unroll
        for (int ni = 0; ni < 8; ni++)
            #pragma unroll
            for (int j = 0; j < 2; j++) {
                float v = ps[ni][j];
                v += __shfl_down_sync(0xffffffffu, v, 16);
                v += __shfl_down_sync(0xffffffffu, v, 8);
                v += __shfl_down_sync(0xffffffffu, v, 4);
                ps[ni][j] = v;
            }
        if (lane < 4) {
            #pragma unroll
            for (int ni = 0; ni < 8; ni++)
                #pragma unroll
                for (int j = 0; j < 2; j++)
                    scr[(warp & 3) * 128 + to + ni * 8 + lane * 2 + j] = ps[ni][j];
        }
        __syncthreads();
        if (tid < TLEN) {
            float s = scr[tid] + scr[128 + tid] + scr[256 + tid] + scr[384 + tid];
            colfac[tid] = 1.0f / (sqrtf(s) + 1e-8f);
        }
        __syncthreads();
        float cf[8][2];
        #pragma unroll
        for (int ni = 0; ni < 8; ni++) {
            cf[ni][0] = colfac[to + ni * 8 + lc * 2];
            cf[ni][1] = colfac[to + ni * 8 + lc * 2 + 1];
        }
        #pragma unroll
        for (int mi = 0; mi < 4; mi++)
            #pragma unroll
            for (int ni = 0; ni < 8; ni++)
                #pragma unroll
                for (int r = 0; r < 4; r++) {
                    int m = mo + mi * 16 + gr + (r >> 1) * 8;
                    int t = to + ni * 8 + lc * 2 + (r & 1);
                    float y = d[mi][ni][r] * cf[ni][r & 1];
                    __nv_bfloat16 hi, lo; split2(y, hi, lo);
                    Bhi[t * SBW + m] = hi; Blo[t * SBW + m] = lo;
                }
        __syncthreads();
    }

    // ======== heads ======== (all cp.async groups drained at step 159)
    float* evw = (float*)(sm + A0_OFF);          // 16x256
    float* sww = evw + CTXD * HID;               // 256
    float* evs = sww + HID;                      // 16x128
    float* attn = evs + CTXD * TLEN;             // 128
    float* redv = (float*)(sm + RV_OFF);
    int*   redi = (int*)(sm + RI_OFF);
    {
        float4* dst = (float4*)evw;
        const float4* src = (const float4*)ev_w;
        #pragma unroll
        for (int i = 0; i < 4; i++) dst[tid + i * 256] = src[tid + i * 256];
        if (tid < 64) ((float4*)sww)[tid] = ((const float4*)sw_w)[tid];
    }
    __syncthreads();
    if (tid < TLEN) {
        float a[CTXD + 1];
        #pragma unroll
        for (int cc = 0; cc < CTXD; cc++) a[cc] = __ldg(ev_b + cc);
        a[CTXD] = __ldg(sw_b);
        for (int i = 0; i < HID; i++) {
            float hv = __bfloat162float(Bhi[tid * SBW + i]) + __bfloat162float(Blo[tid * SBW + i]);
            #pragma unroll
            for (int cc = 0; cc < CTXD; cc++) a[cc] = fmaf(evw[cc * HID + i], hv, a[cc]);
            a[CTXD] = fmaf(sww[i], hv, a[CTXD]);
        }
        #pragma unroll
        for (int cc = 0; cc < CTXD; cc++) evs[cc * TLEN + tid] = a[cc];
        attn[tid] = fmaxf(a[CTXD], 0.f);
    }
    __syncthreads();
    if (tid < TLEN) {
        float v = attn[tid]; int idx = tid;
        #pragma unroll
        for (int off = 16; off > 0; off >>= 1) {
            float ov = __shfl_down_sync(0xffffffffu, v, off);
            int   oi = __shfl_down_sync(0xffffffffu, idx, off);
            if (ov > v || (ov == v && oi < idx)) { v = ov; idx = oi; }
        }
        if (lane == 0) { redv[warp] = v; redi[warp] = idx; }
    }
    __syncthreads();
    if (tid == 0) {
        float v = redv[0]; int idx = redi[0];
        for (int w = 1; w < 4; w++)
            if (redv[w] > v || (redv[w] == v && redi[w] < idx)) { v = redv[w]; idx = redi[w]; }
        redv[0] = v; redi[0] = idx;
    }
    __syncthreads();
    const int bi = redi[0]; const float bv = redv[0];
    if (tid < CTXD) out[(size_t)b * CTXD + tid] = evs[tid * TLEN + bi];
    if (tid < TLEN) out[(size_t)gridDim.x * CTXD + (size_t)b * TLEN + tid] = (tid == bi) ? bv : 0.f;
}

extern "C" void kernel_launch(void* const* d_in, const int* in_sizes, int n_in,
                              void* d_out, int out_size)
{
    const float* x      = (const float*)d_in[0];
    const float* proj_w = (const float*)d_in[1];
    const float* proj_b = (const float*)d_in[2];
    const float* conv_w = (const float*)d_in[3];
    const float* conv_b = (const float*)d_in[4];
    const float* ev_w   = (const float*)d_in[5];
    const float* ev_b   = (const float*)d_in[6];
    const float* sw_w   = (const float*)d_in[7];
    const float* sw_b   = (const float*)d_in[8];
    float* out = (float*)d_out;
    const int B = in_sizes[0] / (1024 * TLEN);   // 256

    prep_kernel<<<160, 256>>>(conv_w, proj_w);
    cudaFuncSetAttribute(Model_26147760898465_kernel,
                         cudaFuncAttributeMaxDynamicSharedMemorySize, SMEM_BYTES);
    Model_26147760898465_kernel<<<B, 256, SMEM_BYTES>>>(
        x, proj_b, conv_b, ev_w, ev_b, sw_w, sw_b, out);
}